// round 12
// baseline (speedup 1.0000x reference)
#include <cuda_runtime.h>
#include <cuda_bf16.h>
#include <math.h>
#include <stdint.h>

#define BATCH 8192
#define D1    129
#define KDIM  128
#define TM    128
#define TN    64
#define NTILE 8192          // 64 rows x 128 cols of 128x64 tiles
#define TOTF  (BATCH * D1)

#define TC_F    1.00000095367431640625f   // fp32(1 + 1e-6)
#define E_CLAMP 0.9804636f                // exp(-acosh(1+2^-20)/0.07)
// R(x) = sqrt(2)*(-C + C/12 x - 3C/160 x^2), C = 1/(0.07 ln2); e = ex2(sqrt(x)*R(x))
#define R0 (-29.1468383f)
#define R1 (2.42890319f)
#define R2 (-0.54650322f)

// smem layout (byte offsets). Rows padded to 272B -> conflict-free ldmatrix.
#define LDT_B    272u
#define SM_A     0u          // A tile: 128*272 = 34816 (shared by both groups, row-resident)
#define SM_B     34816u      // 4 B buffers (group g, buf u at (g*2+u)*17408), 64*272 each
#define B_BUF    17408u
#define SM_A0F   104448u     // a0: 128 floats (row-scoped)
#define SM_B0F   104960u     // b0: 4 x 64 floats (per group x buf)
#define SMEM_BYTES 106240

// ---- device scratch (allocation-free) ----
__device__ __align__(256) __nv_bfloat16 g_A[BATCH * KDIM];
__device__ __align__(256) __nv_bfloat16 g_B[BATCH * KDIM];   // stores -z2 (metric+bias fold)
__device__ float g_a0[BATCH], g_b0[BATCH];
__device__ float g_rowsum[BATCH], g_colsum[BATCH];
__device__ float g_loss;
__device__ unsigned g_bar_cnt;
__device__ volatile unsigned g_bar_gen;

__device__ __forceinline__ uint32_t smem_u32(const void* p) {
    uint32_t a;
    asm("{ .reg .u64 t; cvta.to.shared.u64 t, %1; cvt.u32.u64 %0, t; }" : "=r"(a) : "l"(p));
    return a;
}
__device__ __forceinline__ float f_sqrt(float x) { float r; asm("sqrt.approx.f32 %0, %1;" : "=f"(r) : "f"(x)); return r; }
__device__ __forceinline__ float f_ex2(float x)  { float r; asm("ex2.approx.f32 %0, %1;"  : "=f"(r) : "f"(x)); return r; }

__device__ __forceinline__ void cp_async16(uint32_t dst, const void* src) {
    asm volatile("cp.async.ca.shared.global [%0], [%1], 16;" :: "r"(dst), "l"(src));
}
__device__ __forceinline__ void cp_commit()   { asm volatile("cp.async.commit_group;"); }
__device__ __forceinline__ void cp_wait_all() { asm volatile("cp.async.wait_group 0;"); }
__device__ __forceinline__ void bar_group(int g) {
    asm volatile("bar.sync %0, %1;" :: "r"(g + 1), "r"(128) : "memory");
}

// software grid barrier: all CTAs co-resident (ncta = occ * SMs, verified host-side)
__device__ __forceinline__ void grid_barrier(int ncta) {
    __syncthreads();
    if (threadIdx.x == 0) {
        __threadfence();
        unsigned gen = g_bar_gen;
        if (atomicAdd(&g_bar_cnt, 1u) == (unsigned)(ncta - 1)) {
            g_bar_cnt = 0;
            __threadfence();
            g_bar_gen = gen + 1;
        } else {
            while (g_bar_gen == gen) { __nanosleep(64); }
        }
        __threadfence();
    }
    __syncthreads();
}

__device__ __forceinline__ void ldsm_x4(uint32_t& r0, uint32_t& r1, uint32_t& r2, uint32_t& r3, uint32_t addr) {
    asm volatile("ldmatrix.sync.aligned.m8n8.x4.shared.b16 {%0,%1,%2,%3}, [%4];"
                 : "=r"(r0), "=r"(r1), "=r"(r2), "=r"(r3) : "r"(addr));
}
__device__ __forceinline__ void mma16816(float* c, const uint32_t* a, const uint32_t* b) {
    asm volatile("mma.sync.aligned.m16n8k16.row.col.f32.bf16.bf16.f32 "
                 "{%0,%1,%2,%3}, {%4,%5,%6,%7}, {%8,%9}, {%0,%1,%2,%3};"
                 : "+f"(c[0]), "+f"(c[1]), "+f"(c[2]), "+f"(c[3])
                 : "r"(a[0]), "r"(a[1]), "r"(a[2]), "r"(a[3]), "r"(b[0]), "r"(b[1]));
}

// ---- single persistent kernel: prep -> barrier -> GEMM -> barrier -> loss -> barrier -> write ----
__global__ __launch_bounds__(256, 2) void hyper_fused_kernel(
    const float* __restrict__ z1, const float* __restrict__ z2,
    float* __restrict__ out, int ncta)
{
    extern __shared__ __align__(16) char sm[];
    const uint32_t sbase = smem_u32(sm);
    const int tid  = threadIdx.x;
    const int gid  = blockIdx.x * 256 + tid;
    const int stride = ncta * 256;

    // ===== Phase 1: prep (flat grid-stride, unrolled for MLP) =====
    #pragma unroll 4
    for (int idx = gid; idx < TOTF; idx += stride) {
        int i = idx / D1;
        int k = idx - i * D1;
        float v1 = z1[idx], v2 = z2[idx];
        if (k == 0) { g_a0[i] = v1; g_b0[i] = v2; }
        else {
            g_A[(size_t)i * KDIM + k - 1] = __float2bfloat16(v1);
            g_B[(size_t)i * KDIM + k - 1] = __float2bfloat16(-v2);
        }
    }
    if (gid < BATCH) { g_rowsum[gid] = 0.f; g_colsum[gid] = 0.f; }
    if (gid == 0) g_loss = 0.f;

    grid_barrier(ncta);

    // ===== Phase 2: persistent two-group fused HMMA GEMM + branchless epilogue =====
    {
        const int g    = tid >> 7;          // group 0/1
        const int gtid = tid & 127;
        const int wg   = gtid >> 5;         // warp in group 0..3
        const int lane = tid & 31;

        const int start = (int)(((long long)blockIdx.x * NTILE) / ncta);
        const int end   = (int)(((long long)(blockIdx.x + 1) * NTILE) / ncta);

        const int mw = wg * 32;
        const int lane8 = lane & 7, lm = lane >> 3;
        const int l4 = lane >> 2, l2 = lane & 3;

        const uint32_t aOff = (uint32_t)(mw + ((lm & 1) << 3) + lane8) * LDT_B + (uint32_t)((lm >> 1) << 4);
        const uint32_t bOff = (uint32_t)(((lm >> 1) << 3) + lane8) * LDT_B + (uint32_t)((lm & 1) << 4);

        int pos = start;
        while (pos < end) {
            const int tr = pos >> 7;
            const int r0 = tr * TM;
            const int row_end = min(end, (tr + 1) << 7);

            __syncthreads();                              // both groups done with previous row's A

            // load A strip (all 256 threads) + a0 vector
            #pragma unroll
            for (int it = 0; it < 8; ++it) {
                int idx = tid + it * 256;
                int row = idx >> 4, ch = idx & 15;
                cp_async16(sbase + SM_A + (uint32_t)row * LDT_B + (uint32_t)ch * 16u,
                           g_A + (size_t)(r0 + row) * KDIM + ch * 8);
            }
            if (tid < 32) cp_async16(sbase + SM_A0F + (uint32_t)tid * 16u, g_a0 + r0 + tid * 4);

            // first own tile of this row chunk (parity keyed to start+g)
            const int first = pos + (((start + g) ^ pos) & 1);
            const int n_own = (first < row_end) ? ((row_end - first + 1) >> 1) : 0;

            if (n_own > 0) {
                const int c0 = (first & 127) * TN;
                const uint32_t bb = sbase + SM_B + (uint32_t)(g * 2) * B_BUF;
                #pragma unroll
                for (int it = 0; it < 8; ++it) {
                    int idx = gtid + it * 128;
                    int row = idx >> 4, ch = idx & 15;
                    cp_async16(bb + (uint32_t)row * LDT_B + (uint32_t)ch * 16u,
                               g_B + (size_t)(c0 + row) * KDIM + ch * 8);
                }
                if (gtid < 16)
                    cp_async16(sbase + SM_B0F + (uint32_t)(g * 2) * 256u + (uint32_t)gtid * 16u,
                               g_b0 + c0 + gtid * 4);
            }
            cp_commit();
            cp_wait_all();
            __syncthreads();

            int cur = 0;
            for (int i = 0; i < n_own; ++i) {
                const int t = first + 2 * i;
                const int c0 = (t & 127) * TN;
                const bool more = (i + 1 < n_own);

                if (more) {                               // prefetch next own tile under this compute
                    const int nc0 = ((t + 2) & 127) * TN;
                    const uint32_t bb = sbase + SM_B + (uint32_t)(g * 2 + (cur ^ 1)) * B_BUF;
                    #pragma unroll
                    for (int it = 0; it < 8; ++it) {
                        int idx = gtid + it * 128;
                        int row = idx >> 4, ch = idx & 15;
                        cp_async16(bb + (uint32_t)row * LDT_B + (uint32_t)ch * 16u,
                                   g_B + (size_t)(nc0 + row) * KDIM + ch * 8);
                    }
                    if (gtid < 16)
                        cp_async16(sbase + SM_B0F + (uint32_t)(g * 2 + (cur ^ 1)) * 256u + (uint32_t)gtid * 16u,
                                   g_b0 + nc0 + gtid * 4);
                    cp_commit();
                }

                // ---- MMA ----
                float acc[2][8][4];
                #pragma unroll
                for (int mi = 0; mi < 2; ++mi)
                    #pragma unroll
                    for (int ni = 0; ni < 8; ++ni)
                        #pragma unroll
                        for (int q = 0; q < 4; ++q) acc[mi][ni][q] = -1.0f;   // fold the "-1"

                const uint32_t aBase = sbase + SM_A + aOff;
                const uint32_t bBase = sbase + SM_B + (uint32_t)(g * 2 + cur) * B_BUF + bOff;
                #pragma unroll
                for (int ks = 0; ks < 8; ++ks) {
                    uint32_t a[2][4], b[8][2];
                    ldsm_x4(a[0][0], a[0][1], a[0][2], a[0][3], aBase + ks * 32u);
                    ldsm_x4(a[1][0], a[1][1], a[1][2], a[1][3], aBase + ks * 32u + 16u * LDT_B);
                    #pragma unroll
                    for (int p = 0; p < 4; ++p)
                        ldsm_x4(b[2 * p][0], b[2 * p][1], b[2 * p + 1][0], b[2 * p + 1][1],
                                bBase + ks * 32u + (uint32_t)p * 16u * LDT_B);
                    #pragma unroll
                    for (int mi = 0; mi < 2; ++mi)
                        #pragma unroll
                        for (int ni = 0; ni < 8; ++ni)
                            mma16816(acc[mi][ni], a[mi], b[ni]);
                }

                // ---- epilogue: e = fmin(ex2(sqrt(x)*R(x)), E_CLAMP); x<0 -> NaN -> clamp ----
                const float* sa0 = (const float*)(sm + SM_A0F);
                const float* sb0 = (const float*)(sm + SM_B0F + (g * 2 + cur) * 256);

                float csum[16];
                #pragma unroll
                for (int q = 0; q < 16; ++q) csum[q] = 0.f;
                float rs[4];
                #pragma unroll
                for (int q = 0; q < 4; ++q) rs[q] = 0.f;

                #pragma unroll
                for (int mi = 0; mi < 2; ++mi) {
                    const float a0A = sa0[mw + mi * 16 + l4];
                    const float a0B = sa0[mw + mi * 16 + l4 + 8];
                    #pragma unroll
                    for (int ni = 0; ni < 8; ++ni) {
                        const int colL = ni * 8 + 2 * l2;
                        const float b0L = sb0[colL], b0R = sb0[colL + 1];
                        #pragma unroll
                        for (int q = 0; q < 4; ++q) {
                            const float aa = (q < 2) ? a0A : a0B;
                            const float bb = (q & 1) ? b0R : b0L;
                            float x  = fmaf(aa, bb, acc[mi][ni][q]);   // t - 1
                            float w  = f_sqrt(x);
                            float Rx = fmaf(x, fmaf(x, R2, R1), R0);
                            float e  = fminf(f_ex2(w * Rx), E_CLAMP);
                            rs[mi * 2 + (q >> 1)] += e;
                            csum[ni * 2 + (q & 1)] += e;
                        }
                    }
                }

                #pragma unroll
                for (int q = 0; q < 4; ++q) {
                    float v = rs[q];
                    v += __shfl_xor_sync(0xffffffffu, v, 1);
                    v += __shfl_xor_sync(0xffffffffu, v, 2);
                    if (l2 == 0)
                        atomicAdd(&g_rowsum[r0 + mw + (q >> 1) * 16 + (q & 1) * 8 + l4], v);
                }
                #pragma unroll
                for (int q = 0; q < 16; ++q) {
                    float v = csum[q];
                    v += __shfl_xor_sync(0xffffffffu, v, 4);
                    v += __shfl_xor_sync(0xffffffffu, v, 8);
                    v += __shfl_xor_sync(0xffffffffu, v, 16);
                    if (l4 == 0)
                        atomicAdd(&g_colsum[c0 + (q >> 1) * 8 + 2 * l2 + (q & 1)], v);
                }

                if (more) { cp_wait_all(); bar_group(g); }    // next buffer ready; group done with cur
                cur ^= 1;
            }

            pos = row_end;
        }
    }

    grid_barrier(ncta);

    // ===== Phase 3: loss (first 32 CTAs) =====
    {
        float* red = (float*)sm;
        if (gid < BATCH) {
            float dotn = 0.f;                              // accumulates -dot (g_B negated)
            const __nv_bfloat16* pa = g_A + (size_t)gid * KDIM;
            const __nv_bfloat16* pb = g_B + (size_t)gid * KDIM;
            #pragma unroll 8
            for (int k = 0; k < KDIM; ++k)
                dotn = fmaf(__bfloat162float(pa[k]), __bfloat162float(pb[k]), dotn);
            float t = fmaxf(fmaf(g_a0[gid], g_b0[gid], dotn), TC_F);
            float s_ii = -acoshf(t) * (1.0f / 0.07f);

            float part = 0.5f * (logf(g_rowsum[gid]) + logf(g_colsum[gid])) - s_ii;
            red[tid] = part;
            __syncthreads();
            for (int s = 128; s > 0; s >>= 1) {
                if (tid < s) red[tid] += red[tid + s];
                __syncthreads();
            }
            if (tid == 0) atomicAdd(&g_loss, red[0]);
        }
    }

    grid_barrier(ncta);

    // ===== Phase 4: write scalar =====
    if (gid == 0) out[0] = atomicAdd(&g_loss, 0.0f) * (1.0f / (float)BATCH);
}

extern "C" void kernel_launch(void* const* d_in, const int* in_sizes, int n_in,
                              void* d_out, int out_size) {
    const float* z1 = (const float*)d_in[0];
    const float* z2 = (const float*)d_in[1];
    float* out = (float*)d_out;

    static int ncta = 0;
    if (ncta == 0) {
        cudaFuncSetAttribute(hyper_fused_kernel, cudaFuncAttributeMaxDynamicSharedMemorySize, SMEM_BYTES);
        int sms = 0;
        if (cudaDeviceGetAttribute(&sms, cudaDevAttrMultiProcessorCount, 0) != cudaSuccess || sms <= 0)
            sms = 148;
        int occ = 0;
        if (cudaOccupancyMaxActiveBlocksPerMultiprocessor(&occ, hyper_fused_kernel, 256, SMEM_BYTES)
                != cudaSuccess || occ <= 0)
            occ = 1;                          // conservative: barrier-safe
        if (occ > 2) occ = 2;
        ncta = occ * sms;                     // all CTAs provably co-resident
        if (ncta > NTILE) ncta = NTILE;
    }

    hyper_fused_kernel<<<ncta, 256, SMEM_BYTES>>>(z1, z2, out, ncta);
}

// round 13
// speedup vs baseline: 1.0009x; 1.0009x over previous
#include <cuda_runtime.h>
#include <cuda_bf16.h>
#include <math.h>
#include <stdint.h>

#define BATCH 8192
#define D1    129
#define KDIM  128
#define TM    128
#define TN    64
#define NTILE 8192          // 64 tile-rows x 128 tile-cols of 128x64 tiles

#define TC_F    1.00000095367431640625f   // fp32(1 + 1e-6)
#define E_CLAMP 0.9804636f                // exp(-acosh(1+2^-20)/0.07)
// R(x) = sqrt(2)*(-C + C/12 x - 3C/160 x^2), C = 1/(0.07 ln2); e = ex2(sqrt(x)*R(x))
#define R0 (-29.1468383f)
#define R1 (2.42890319f)
#define R2 (-0.54650322f)

// smem layout (byte offsets). Rows padded to 272B -> conflict-free ldmatrix.
#define LDT_B    272u
#define SM_A     0u          // A strip: 128*272 = 34816 (row-chunk resident)
#define SM_BB0   34816u      // B buf0: 64*272 = 17408
#define SM_BB1   52224u      // B buf1
#define SM_A0F   69632u      // a0: 128 floats
#define SM_B0F   70144u      // b0: 2 x 64 floats
#define SMEM_BYTES 70656     // x3 CTAs = 212KB <= 227KB/SM

// ---- device scratch (allocation-free) ----
__device__ __align__(256) __nv_bfloat16 g_A[BATCH * KDIM];
__device__ __align__(256) __nv_bfloat16 g_B[BATCH * KDIM];   // stores -z2 (metric+bias fold)
__device__ float g_a0[BATCH], g_b0[BATCH];
__device__ float g_rowsum[BATCH], g_colsum[BATCH];
__device__ float g_loss;
__device__ unsigned g_ticket;

__device__ __forceinline__ uint32_t smem_u32(const void* p) {
    uint32_t a;
    asm("{ .reg .u64 t; cvta.to.shared.u64 t, %1; cvt.u32.u64 %0, t; }" : "=r"(a) : "l"(p));
    return a;
}
__device__ __forceinline__ float f_sqrt(float x) { float r; asm("sqrt.approx.f32 %0, %1;" : "=f"(r) : "f"(x)); return r; }
__device__ __forceinline__ float f_ex2(float x)  { float r; asm("ex2.approx.f32 %0, %1;"  : "=f"(r) : "f"(x)); return r; }

__device__ __forceinline__ void cp_async16(uint32_t dst, const void* src) {
    asm volatile("cp.async.ca.shared.global [%0], [%1], 16;" :: "r"(dst), "l"(src));
}
__device__ __forceinline__ void cp_commit()   { asm volatile("cp.async.commit_group;"); }
__device__ __forceinline__ void cp_wait_all() { asm volatile("cp.async.wait_group 0;"); }

__device__ __forceinline__ void ldsm_x4(uint32_t& r0, uint32_t& r1, uint32_t& r2, uint32_t& r3, uint32_t addr) {
    asm volatile("ldmatrix.sync.aligned.m8n8.x4.shared.b16 {%0,%1,%2,%3}, [%4];"
                 : "=r"(r0), "=r"(r1), "=r"(r2), "=r"(r3) : "r"(addr));
}
__device__ __forceinline__ void mma16816(float* c, const uint32_t* a, const uint32_t* b) {
    asm volatile("mma.sync.aligned.m16n8k16.row.col.f32.bf16.bf16.f32 "
                 "{%0,%1,%2,%3}, {%4,%5,%6,%7}, {%8,%9}, {%0,%1,%2,%3};"
                 : "+f"(c[0]), "+f"(c[1]), "+f"(c[2]), "+f"(c[3])
                 : "r"(a[0]), "r"(a[1]), "r"(a[2]), "r"(a[3]), "r"(b[0]), "r"(b[1]));
}

// ---- prep: flat coalesced pass over the 129-stride inputs ----
__global__ void prep_kernel(const float* __restrict__ z1, const float* __restrict__ z2) {
    int idx = blockIdx.x * 256 + threadIdx.x;
    if (idx < BATCH * D1) {
        int i = idx / D1;
        int k = idx - i * D1;
        float v1 = z1[idx], v2 = z2[idx];
        if (k == 0) { g_a0[i] = v1; g_b0[i] = v2; }
        else {
            g_A[(size_t)i * KDIM + k - 1] = __float2bfloat16(v1);
            g_B[(size_t)i * KDIM + k - 1] = __float2bfloat16(-v2);
        }
    }
    if (idx < BATCH) { g_rowsum[idx] = 0.f; g_colsum[idx] = 0.f; }
    if (idx == 0) { g_loss = 0.f; g_ticket = 0u; }
}

// ---- persistent fused HMMA GEMM + branchless epilogue; 16x64 warp tiles, occ 3 ----
__global__ __launch_bounds__(256, 3) void hyper_gemm_kernel(int ncta) {
    extern __shared__ __align__(16) char sm[];
    const uint32_t sbase = smem_u32(sm);
    const int tid  = threadIdx.x;
    const int wid  = tid >> 5;
    const int lane = tid & 31;

    const int start = (int)(((long long)blockIdx.x * NTILE) / ncta);
    const int end   = (int)(((long long)(blockIdx.x + 1) * NTILE) / ncta);

    const int mw = wid * 16;                 // 8 warps x 16 rows = 128
    const int lane8 = lane & 7, lm = lane >> 3;
    const int l4 = lane >> 2, l2 = lane & 3;

    const uint32_t aOff = (uint32_t)(mw + ((lm & 1) << 3) + lane8) * LDT_B + (uint32_t)((lm >> 1) << 4);
    const uint32_t bOff = (uint32_t)(((lm >> 1) << 3) + lane8) * LDT_B + (uint32_t)((lm & 1) << 4);

    int pos = start;
    while (pos < end) {
        const int tr = pos >> 7;
        const int r0 = tr * TM;
        const int row_end = min(end, (tr + 1) << 7);

        __syncthreads();                     // all warps done with previous chunk's A

        // A strip (128 rows) + a0
        #pragma unroll
        for (int it = 0; it < 8; ++it) {
            int idx = tid + it * 256;
            int row = idx >> 4, ch = idx & 15;
            cp_async16(sbase + SM_A + (uint32_t)row * LDT_B + (uint32_t)ch * 16u,
                       g_A + (size_t)(r0 + row) * KDIM + ch * 8);
        }
        if (tid < 32) cp_async16(sbase + SM_A0F + (uint32_t)tid * 16u, g_a0 + r0 + tid * 4);

        // first B tile of the chunk
        {
            const int c0 = (pos & 127) * TN;
            #pragma unroll
            for (int it = 0; it < 4; ++it) {
                int idx = tid + it * 256;
                int row = idx >> 4, ch = idx & 15;
                cp_async16(sbase + SM_BB0 + (uint32_t)row * LDT_B + (uint32_t)ch * 16u,
                           g_B + (size_t)(c0 + row) * KDIM + ch * 8);
            }
            if (tid < 16) cp_async16(sbase + SM_B0F + (uint32_t)tid * 16u, g_b0 + c0 + tid * 4);
        }
        cp_commit();
        cp_wait_all();
        __syncthreads();

        const float* sa0 = (const float*)(sm + SM_A0F);
        const float a0A = sa0[mw + l4];
        const float a0B = sa0[mw + l4 + 8];
        float rs0 = 0.f, rs1 = 0.f;          // rowsum partials, held across the whole chunk

        int cur = 0;
        for (int t = pos; t < row_end; ++t) {
            const int c0 = (t & 127) * TN;
            const bool more = (t + 1 < row_end);

            if (more) {                      // prefetch next B under this tile's compute
                const int nc0 = ((t + 1) & 127) * TN;
                const uint32_t bb = sbase + (cur ? SM_BB0 : SM_BB1);
                #pragma unroll
                for (int it = 0; it < 4; ++it) {
                    int idx = tid + it * 256;
                    int row = idx >> 4, ch = idx & 15;
                    cp_async16(bb + (uint32_t)row * LDT_B + (uint32_t)ch * 16u,
                               g_B + (size_t)(nc0 + row) * KDIM + ch * 8);
                }
                if (tid < 16)
                    cp_async16(sbase + SM_B0F + (uint32_t)(cur ^ 1) * 256u + (uint32_t)tid * 16u,
                               g_b0 + nc0 + tid * 4);
                cp_commit();
            }

            // ---- MMA: warp tile 16x64, acc 32 regs ----
            float acc[8][4];
            #pragma unroll
            for (int ni = 0; ni < 8; ++ni)
                #pragma unroll
                for (int q = 0; q < 4; ++q) acc[ni][q] = -1.0f;   // fold the "-1"

            const uint32_t aBase = sbase + SM_A + aOff;
            const uint32_t bBase = sbase + (cur ? SM_BB1 : SM_BB0) + bOff;
            #pragma unroll
            for (int ks = 0; ks < 8; ++ks) {
                uint32_t a[4], b[8][2];
                ldsm_x4(a[0], a[1], a[2], a[3], aBase + ks * 32u);
                #pragma unroll
                for (int p = 0; p < 4; ++p)
                    ldsm_x4(b[2 * p][0], b[2 * p][1], b[2 * p + 1][0], b[2 * p + 1][1],
                            bBase + ks * 32u + (uint32_t)p * 16u * LDT_B);
                #pragma unroll
                for (int ni = 0; ni < 8; ++ni)
                    mma16816(acc[ni], a, b[ni]);
            }

            // ---- epilogue: e = fmin(ex2(sqrt(x)*R(x)), E_CLAMP); x<0 -> NaN -> clamp ----
            const float* sb0 = (const float*)(sm + SM_B0F + cur * 256);
            float csum[16];
            #pragma unroll
            for (int q = 0; q < 16; ++q) csum[q] = 0.f;

            #pragma unroll
            for (int ni = 0; ni < 8; ++ni) {
                const int colL = ni * 8 + 2 * l2;
                const float b0L = sb0[colL], b0R = sb0[colL + 1];
                #pragma unroll
                for (int q = 0; q < 4; ++q) {
                    const float aa = (q < 2) ? a0A : a0B;
                    const float bb = (q & 1) ? b0R : b0L;
                    float x  = fmaf(aa, bb, acc[ni][q]);   // t - 1
                    float w  = f_sqrt(x);
                    float Rx = fmaf(x, fmaf(x, R2, R1), R0);
                    float e  = fminf(f_ex2(w * Rx), E_CLAMP);
                    if (q < 2) rs0 += e; else rs1 += e;
                    csum[ni * 2 + (q & 1)] += e;
                }
            }

            #pragma unroll
            for (int q = 0; q < 16; ++q) {
                float v = csum[q];
                v += __shfl_xor_sync(0xffffffffu, v, 4);
                v += __shfl_xor_sync(0xffffffffu, v, 8);
                v += __shfl_xor_sync(0xffffffffu, v, 16);
                if (l4 == 0)
                    atomicAdd(&g_colsum[c0 + (q >> 1) * 8 + 2 * l2 + (q & 1)], v);
            }

            if (more) { cp_wait_all(); __syncthreads(); }
            cur ^= 1;
        }

        // rowsum commit: once per chunk
        {
            float v = rs0;
            v += __shfl_xor_sync(0xffffffffu, v, 1);
            v += __shfl_xor_sync(0xffffffffu, v, 2);
            if (l2 == 0) atomicAdd(&g_rowsum[r0 + mw + l4], v);
            v = rs1;
            v += __shfl_xor_sync(0xffffffffu, v, 1);
            v += __shfl_xor_sync(0xffffffffu, v, 2);
            if (l2 == 0) atomicAdd(&g_rowsum[r0 + mw + 8 + l4], v);
        }

        pos = row_end;
    }
}

// ---- loss: diag + log-sums + ticket-gated finalize ----
__global__ void loss_kernel(float* __restrict__ out) {
    __shared__ float red[256];
    const int i = blockIdx.x * 256 + threadIdx.x;

    float dotn = 0.f;                                  // accumulates -dot (g_B negated)
    const __nv_bfloat16* pa = g_A + (size_t)i * KDIM;
    const __nv_bfloat16* pb = g_B + (size_t)i * KDIM;
    #pragma unroll 8
    for (int k = 0; k < KDIM; ++k)
        dotn = fmaf(__bfloat162float(pa[k]), __bfloat162float(pb[k]), dotn);
    float t = fmaxf(fmaf(g_a0[i], g_b0[i], dotn), TC_F);
    float s_ii = -acoshf(t) * (1.0f / 0.07f);

    float part = 0.5f * (logf(g_rowsum[i]) + logf(g_colsum[i])) - s_ii;
    red[threadIdx.x] = part;
    __syncthreads();
    for (int s = 128; s > 0; s >>= 1) {
        if (threadIdx.x < s) red[threadIdx.x] += red[threadIdx.x + s];
        __syncthreads();
    }
    if (threadIdx.x == 0) {
        atomicAdd(&g_loss, red[0]);
        __threadfence();
        unsigned tk = atomicAdd(&g_ticket, 1u);
        if (tk == gridDim.x - 1) {
            float total = atomicAdd(&g_loss, 0.0f);
            out[0] = total * (1.0f / (float)BATCH);
        }
    }
}

extern "C" void kernel_launch(void* const* d_in, const int* in_sizes, int n_in,
                              void* d_out, int out_size) {
    const float* z1 = (const float*)d_in[0];
    const float* z2 = (const float*)d_in[1];
    float* out = (float*)d_out;

    static int ncta = 0;
    if (ncta == 0) {
        cudaFuncSetAttribute(hyper_gemm_kernel, cudaFuncAttributeMaxDynamicSharedMemorySize, SMEM_BYTES);
        int sms = 0;
        if (cudaDeviceGetAttribute(&sms, cudaDevAttrMultiProcessorCount, 0) != cudaSuccess || sms <= 0)
            sms = 148;
        int occ = 0;
        if (cudaOccupancyMaxActiveBlocksPerMultiprocessor(&occ, hyper_gemm_kernel, 256, SMEM_BYTES)
                != cudaSuccess || occ <= 0)
            occ = 2;
        ncta = occ * sms;
        if (ncta > NTILE) ncta = NTILE;
    }

    prep_kernel<<<(BATCH * D1 + 255) / 256, 256>>>(z1, z2);
    hyper_gemm_kernel<<<ncta, 256, SMEM_BYTES>>>(ncta);
    loss_kernel<<<BATCH / 256, 256>>>(out);
}

// round 14
// speedup vs baseline: 1.1183x; 1.1172x over previous
#include <cuda_runtime.h>
#include <cuda_bf16.h>
#include <math.h>
#include <stdint.h>

#define BATCH 8192
#define D1    129
#define KDIM  128
#define TM    128
#define TN    64
#define NTILE 8192          // 64 rows x 128 cols of 128x64 tiles

#define TC_F    1.00000095367431640625f   // fp32(1 + 1e-6)
#define E_CLAMP 0.9804636f                // exp(-acosh(1+2^-20)/0.07)
// R(x) = sqrt(2)*(-C + C/12 x - 3C/160 x^2), C = 1/(0.07 ln2); e = ex2(sqrt(x)*R(x))
#define RC0 (-29.1468383f)
#define RC1 (2.42890319f)
#define RC2 (-0.54650322f)

// smem layout (byte offsets). Rows padded to 272B -> conflict-free ldmatrix.
#define LDT_B    272u
#define SM_A     0u          // A tile: 128*272 = 34816 (shared by both groups, row-resident)
#define SM_B     34816u      // 4 B buffers (group g, buf u at (g*2+u)*17408), 64*272 each
#define B_BUF    17408u
#define SM_A0F   104448u     // a0: 128 floats (row-scoped)
#define SM_B0F   104960u     // b0: 4 x 64 floats (per group x buf)
#define SMEM_BYTES 106240

// ---- device scratch (allocation-free) ----
__device__ __align__(256) __nv_bfloat16 g_A[BATCH * KDIM];
__device__ __align__(256) __nv_bfloat16 g_B[BATCH * KDIM];   // stores -z2 (metric+bias fold)
__device__ float g_a0[BATCH], g_b0[BATCH];
__device__ float g_rowsum[BATCH], g_colsum[BATCH];
__device__ float g_loss;
__device__ unsigned g_ticket;

__device__ __forceinline__ uint32_t smem_u32(const void* p) {
    uint32_t a;
    asm("{ .reg .u64 t; cvta.to.shared.u64 t, %1; cvt.u32.u64 %0, t; }" : "=r"(a) : "l"(p));
    return a;
}
__device__ __forceinline__ float f_sqrt(float x) { float r; asm("sqrt.approx.f32 %0, %1;" : "=f"(r) : "f"(x)); return r; }
__device__ __forceinline__ float f_ex2(float x)  { float r; asm("ex2.approx.f32 %0, %1;"  : "=f"(r) : "f"(x)); return r; }

// ---- packed f32x2 (Blackwell, family-portable PTX: requires sm_100+, not sm_100a) ----
__device__ __forceinline__ uint64_t pk2(float lo, float hi) {
    uint64_t r; asm("mov.b64 %0, {%1, %2};" : "=l"(r) : "f"(lo), "f"(hi)); return r;
}
__device__ __forceinline__ void upk2(float& lo, float& hi, uint64_t v) {
    asm("mov.b64 {%0, %1}, %2;" : "=f"(lo), "=f"(hi) : "l"(v));
}
__device__ __forceinline__ uint64_t fma2(uint64_t a, uint64_t b, uint64_t c) {
    uint64_t d; asm("fma.rn.f32x2 %0, %1, %2, %3;" : "=l"(d) : "l"(a), "l"(b), "l"(c)); return d;
}
__device__ __forceinline__ uint64_t mul2(uint64_t a, uint64_t b) {
    uint64_t d; asm("mul.rn.f32x2 %0, %1, %2;" : "=l"(d) : "l"(a), "l"(b)); return d;
}
__device__ __forceinline__ uint64_t add2(uint64_t a, uint64_t b) {
    uint64_t d; asm("add.rn.f32x2 %0, %1, %2;" : "=l"(d) : "l"(a), "l"(b)); return d;
}

__device__ __forceinline__ void cp_async16(uint32_t dst, const void* src) {
    asm volatile("cp.async.ca.shared.global [%0], [%1], 16;" :: "r"(dst), "l"(src));
}
__device__ __forceinline__ void cp_commit()   { asm volatile("cp.async.commit_group;"); }
__device__ __forceinline__ void cp_wait_all() { asm volatile("cp.async.wait_group 0;"); }
__device__ __forceinline__ void bar_group(int g) {
    asm volatile("bar.sync %0, %1;" :: "r"(g + 1), "r"(128) : "memory");
}

__device__ __forceinline__ void ldsm_x4(uint32_t& r0, uint32_t& r1, uint32_t& r2, uint32_t& r3, uint32_t addr) {
    asm volatile("ldmatrix.sync.aligned.m8n8.x4.shared.b16 {%0,%1,%2,%3}, [%4];"
                 : "=r"(r0), "=r"(r1), "=r"(r2), "=r"(r3) : "r"(addr));
}
__device__ __forceinline__ void mma16816(float* c, const uint32_t* a, const uint32_t* b) {
    asm volatile("mma.sync.aligned.m16n8k16.row.col.f32.bf16.bf16.f32 "
                 "{%0,%1,%2,%3}, {%4,%5,%6,%7}, {%8,%9}, {%0,%1,%2,%3};"
                 : "+f"(c[0]), "+f"(c[1]), "+f"(c[2]), "+f"(c[3])
                 : "r"(a[0]), "r"(a[1]), "r"(a[2]), "r"(a[3]), "r"(b[0]), "r"(b[1]));
}

// ---- prep: flat coalesced pass over the 129-stride inputs ----
__global__ void prep_kernel(const float* __restrict__ z1, const float* __restrict__ z2) {
    int idx = blockIdx.x * 256 + threadIdx.x;
    if (idx < BATCH * D1) {
        int i = idx / D1;
        int k = idx - i * D1;
        float v1 = z1[idx], v2 = z2[idx];
        if (k == 0) { g_a0[i] = v1; g_b0[i] = v2; }
        else {
            g_A[(size_t)i * KDIM + k - 1] = __float2bfloat16(v1);
            g_B[(size_t)i * KDIM + k - 1] = __float2bfloat16(-v2);
        }
    }
    if (idx < BATCH) { g_rowsum[idx] = 0.f; g_colsum[idx] = 0.f; }
    if (idx == 0) { g_loss = 0.f; g_ticket = 0u; }
}

// ---- persistent two-group fused HMMA GEMM + packed-f32x2 epilogue ----
__global__ __launch_bounds__(256, 2) void hyper_gemm_kernel(int ncta) {
    extern __shared__ __align__(16) char sm[];
    const uint32_t sbase = smem_u32(sm);
    const int tid  = threadIdx.x;
    const int g    = tid >> 7;          // group 0/1
    const int gtid = tid & 127;
    const int wg   = gtid >> 5;         // warp in group 0..3
    const int lane = tid & 31;

    const int start = (int)(((long long)blockIdx.x * NTILE) / ncta);
    const int end   = (int)(((long long)(blockIdx.x + 1) * NTILE) / ncta);

    const int mw = wg * 32;
    const int lane8 = lane & 7, lm = lane >> 3;
    const int l4 = lane >> 2, l2 = lane & 3;

    const uint32_t aOff = (uint32_t)(mw + ((lm & 1) << 3) + lane8) * LDT_B + (uint32_t)((lm >> 1) << 4);
    const uint32_t bOff = (uint32_t)(((lm >> 1) << 3) + lane8) * LDT_B + (uint32_t)((lm & 1) << 4);

    const uint64_t R0p = pk2(RC0, RC0), R1p = pk2(RC1, RC1), R2p = pk2(RC2, RC2);

    int pos = start;
    while (pos < end) {
        const int tr = pos >> 7;
        const int r0 = tr * TM;
        const int row_end = min(end, (tr + 1) << 7);

        __syncthreads();                              // both groups done with previous row's A

        // load A strip (all 256 threads) + a0 vector
        #pragma unroll
        for (int it = 0; it < 8; ++it) {
            int idx = tid + it * 256;
            int row = idx >> 4, ch = idx & 15;
            cp_async16(sbase + SM_A + (uint32_t)row * LDT_B + (uint32_t)ch * 16u,
                       g_A + (size_t)(r0 + row) * KDIM + ch * 8);
        }
        if (tid < 32) cp_async16(sbase + SM_A0F + (uint32_t)tid * 16u, g_a0 + r0 + tid * 4);

        // first own tile of this row chunk (parity keyed to start+g)
        const int first = pos + (((start + g) ^ pos) & 1);
        const int n_own = (first < row_end) ? ((row_end - first + 1) >> 1) : 0;

        if (n_own > 0) {
            const int c0 = (first & 127) * TN;
            const uint32_t bb = sbase + SM_B + (uint32_t)(g * 2) * B_BUF;
            #pragma unroll
            for (int it = 0; it < 8; ++it) {
                int idx = gtid + it * 128;
                int row = idx >> 4, ch = idx & 15;
                cp_async16(bb + (uint32_t)row * LDT_B + (uint32_t)ch * 16u,
                           g_B + (size_t)(c0 + row) * KDIM + ch * 8);
            }
            if (gtid < 16)
                cp_async16(sbase + SM_B0F + (uint32_t)(g * 2) * 256u + (uint32_t)gtid * 16u,
                           g_b0 + c0 + gtid * 4);
        }
        cp_commit();
        cp_wait_all();
        __syncthreads();

        int cur = 0;
        for (int i = 0; i < n_own; ++i) {
            const int t = first + 2 * i;
            const int c0 = (t & 127) * TN;
            const bool more = (i + 1 < n_own);

            if (more) {                               // prefetch next own tile under this compute
                const int nc0 = ((t + 2) & 127) * TN;
                const uint32_t bb = sbase + SM_B + (uint32_t)(g * 2 + (cur ^ 1)) * B_BUF;
                #pragma unroll
                for (int it = 0; it < 8; ++it) {
                    int idx = gtid + it * 128;
                    int row = idx >> 4, ch = idx & 15;
                    cp_async16(bb + (uint32_t)row * LDT_B + (uint32_t)ch * 16u,
                               g_B + (size_t)(nc0 + row) * KDIM + ch * 8);
                }
                if (gtid < 16)
                    cp_async16(sbase + SM_B0F + (uint32_t)(g * 2 + (cur ^ 1)) * 256u + (uint32_t)gtid * 16u,
                               g_b0 + nc0 + gtid * 4);
                cp_commit();
            }

            // ---- MMA ----
            float acc[2][8][4];
            #pragma unroll
            for (int mi = 0; mi < 2; ++mi)
                #pragma unroll
                for (int ni = 0; ni < 8; ++ni)
                    #pragma unroll
                    for (int q = 0; q < 4; ++q) acc[mi][ni][q] = -1.0f;   // fold the "-1"

            const uint32_t aBase = sbase + SM_A + aOff;
            const uint32_t bBase = sbase + SM_B + (uint32_t)(g * 2 + cur) * B_BUF + bOff;
            #pragma unroll
            for (int ks = 0; ks < 8; ++ks) {
                uint32_t a[2][4], b[8][2];
                ldsm_x4(a[0][0], a[0][1], a[0][2], a[0][3], aBase + ks * 32u);
                ldsm_x4(a[1][0], a[1][1], a[1][2], a[1][3], aBase + ks * 32u + 16u * LDT_B);
                #pragma unroll
                for (int p = 0; p < 4; ++p)
                    ldsm_x4(b[2 * p][0], b[2 * p][1], b[2 * p + 1][0], b[2 * p + 1][1],
                            bBase + ks * 32u + (uint32_t)p * 16u * LDT_B);
                #pragma unroll
                for (int mi = 0; mi < 2; ++mi)
                    #pragma unroll
                    for (int ni = 0; ni < 8; ++ni)
                        mma16816(acc[mi][ni], a[mi], b[ni]);
            }

            // ---- packed epilogue: per pair {q,q+1}: x2=fma2; e=fmin(ex2(sqrt*R)) per half ----
            const float* sa0 = (const float*)(sm + SM_A0F);
            const float* sb0 = (const float*)(sm + SM_B0F + (g * 2 + cur) * 256);

            uint64_t csum2[8];
            #pragma unroll
            for (int q = 0; q < 8; ++q) csum2[q] = 0ull;
            uint64_t rs2[4];
            #pragma unroll
            for (int q = 0; q < 4; ++q) rs2[q] = 0ull;

            #pragma unroll
            for (int mi = 0; mi < 2; ++mi) {
                const float a0A = sa0[mw + mi * 16 + l4];
                const float a0B = sa0[mw + mi * 16 + l4 + 8];
                const uint64_t aA2 = pk2(a0A, a0A);
                const uint64_t aB2 = pk2(a0B, a0B);
                #pragma unroll
                for (int ni = 0; ni < 8; ++ni) {
                    const int colL = ni * 8 + 2 * l2;
                    const uint64_t b2 = pk2(sb0[colL], sb0[colL + 1]);
                    #pragma unroll
                    for (int p = 0; p < 2; ++p) {      // p=0: rows A (q0,q1); p=1: rows B (q2,q3)
                        const uint64_t acc2 = pk2(acc[mi][ni][2 * p], acc[mi][ni][2 * p + 1]);
                        const uint64_t x2 = fma2(p ? aB2 : aA2, b2, acc2);   // {t-1} pair
                        float x0, x1; upk2(x0, x1, x2);
                        const float w0 = f_sqrt(x0), w1 = f_sqrt(x1);
                        const uint64_t Rx2 = fma2(x2, fma2(x2, R2p, R1p), R0p);
                        const uint64_t m2 = mul2(pk2(w0, w1), Rx2);
                        float m0, m1; upk2(m0, m1, m2);
                        const float e0 = fminf(f_ex2(m0), E_CLAMP);   // x<0 -> NaN -> clamp
                        const float e1 = fminf(f_ex2(m1), E_CLAMP);
                        const uint64_t e2 = pk2(e0, e1);
                        rs2[mi * 2 + p] = add2(rs2[mi * 2 + p], e2);
                        csum2[ni] = add2(csum2[ni], e2);
                    }
                }
            }

            #pragma unroll
            for (int q = 0; q < 4; ++q) {
                float lo, hi; upk2(lo, hi, rs2[q]);
                float v = lo + hi;
                v += __shfl_xor_sync(0xffffffffu, v, 1);
                v += __shfl_xor_sync(0xffffffffu, v, 2);
                if (l2 == 0)
                    atomicAdd(&g_rowsum[r0 + mw + (q >> 1) * 16 + (q & 1) * 8 + l4], v);
            }
            #pragma unroll
            for (int ni = 0; ni < 8; ++ni) {
                float lo, hi; upk2(lo, hi, csum2[ni]);
                #pragma unroll
                for (int h = 0; h < 2; ++h) {
                    float v = h ? hi : lo;
                    v += __shfl_xor_sync(0xffffffffu, v, 4);
                    v += __shfl_xor_sync(0xffffffffu, v, 8);
                    v += __shfl_xor_sync(0xffffffffu, v, 16);
                    if (l4 == 0)
                        atomicAdd(&g_colsum[c0 + ni * 8 + 2 * l2 + h], v);
                }
            }

            if (more) { cp_wait_all(); bar_group(g); }    // next buffer ready; group done with cur
            cur ^= 1;
        }

        pos = row_end;
    }
}

// ---- loss: diag + log-sums + ticket-gated finalize ----
__global__ void loss_kernel(float* __restrict__ out) {
    __shared__ float red[256];
    const int i = blockIdx.x * 256 + threadIdx.x;

    float dotn = 0.f;                                  // accumulates -dot (g_B negated)
    const __nv_bfloat16* pa = g_A + (size_t)i * KDIM;
    const __nv_bfloat16* pb = g_B + (size_t)i * KDIM;
    #pragma unroll 8
    for (int k = 0; k < KDIM; ++k)
        dotn = fmaf(__bfloat162float(pa[k]), __bfloat162float(pb[k]), dotn);
    float t = fmaxf(fmaf(g_a0[i], g_b0[i], dotn), TC_F);
    float s_ii = -acoshf(t) * (1.0f / 0.07f);

    float part = 0.5f * (logf(g_rowsum[i]) + logf(g_colsum[i])) - s_ii;
    red[threadIdx.x] = part;
    __syncthreads();
    for (int s = 128; s > 0; s >>= 1) {
        if (threadIdx.x < s) red[threadIdx.x] += red[threadIdx.x + s];
        __syncthreads();
    }
    if (threadIdx.x == 0) {
        atomicAdd(&g_loss, red[0]);
        __threadfence();
        unsigned tk = atomicAdd(&g_ticket, 1u);
        if (tk == gridDim.x - 1) {
            float total = atomicAdd(&g_loss, 0.0f);
            out[0] = total * (1.0f / (float)BATCH);
        }
    }
}

extern "C" void kernel_launch(void* const* d_in, const int* in_sizes, int n_in,
                              void* d_out, int out_size) {
    const float* z1 = (const float*)d_in[0];
    const float* z2 = (const float*)d_in[1];
    float* out = (float*)d_out;

    static int ncta = 0;
    if (ncta == 0) {
        int sms = 0;
        if (cudaDeviceGetAttribute(&sms, cudaDevAttrMultiProcessorCount, 0) != cudaSuccess || sms <= 0)
            sms = 148;
        ncta = 2 * sms;
        if (ncta > NTILE) ncta = NTILE;
        cudaFuncSetAttribute(hyper_gemm_kernel, cudaFuncAttributeMaxDynamicSharedMemorySize, SMEM_BYTES);
    }

    prep_kernel<<<(BATCH * D1 + 255) / 256, 256>>>(z1, z2);
    hyper_gemm_kernel<<<ncta, 256, SMEM_BYTES>>>(ncta);
    loss_kernel<<<BATCH / 256, 256>>>(out);
}

// round 17
// speedup vs baseline: 1.1923x; 1.0662x over previous
#include <cuda_runtime.h>
#include <cuda_bf16.h>
#include <math.h>
#include <stdint.h>

#define BATCH 8192
#define D1    129
#define KDIM  128
#define TM    128
#define TN    64
#define NTILE 8192          // 64 rows x 128 cols of 128x64 tiles
#define TOTF  (BATCH * D1)
#define PREP_BLOCKS 1184

#define TC_F    1.00000095367431640625f   // fp32(1 + 1e-6)
#define E_CLAMP 0.9804636f                // exp(-acosh(1+2^-20)/0.07)
// R(x) = sqrt(2)*(-C + C/12 x - 3C/160 x^2), C = 1/(0.07 ln2); e = ex2(sqrt(x)*R(x))
#define RC0 (-29.1468383f)
#define RC1 (2.42890319f)
#define RC2 (-0.54650322f)

// smem layout (byte offsets). Rows padded to 272B -> conflict-free ldmatrix.
#define LDT_B    272u
#define SM_A     0u          // A tile: 128*272 = 34816 (shared by both groups, row-resident)
#define SM_B     34816u      // 4 B buffers (group g, buf u at (g*2+u)*17408), 64*272 each
#define B_BUF    17408u
#define SM_A0F   104448u     // a0: 128 floats (row-scoped)
#define SM_B0F   104960u     // b0: 4 x 64 floats (per group x buf)
#define SMEM_BYTES 106240

// ---- device scratch (allocation-free) ----
__device__ __align__(256) __nv_bfloat16 g_A[BATCH * KDIM];
__device__ __align__(256) __nv_bfloat16 g_B[BATCH * KDIM];   // stores -z2 (metric+bias fold)
__device__ float g_a0[BATCH], g_b0[BATCH];
__device__ float g_rowsum[BATCH], g_colsum[BATCH];
__device__ float g_diag[BATCH];                               // x_ii = t_ii - 1 from the GEMM
__device__ float g_loss;
__device__ unsigned g_ticket;

__device__ __forceinline__ uint32_t smem_u32(const void* p) {
    uint32_t a;
    asm("{ .reg .u64 t; cvta.to.shared.u64 t, %1; cvt.u32.u64 %0, t; }" : "=r"(a) : "l"(p));
    return a;
}
__device__ __forceinline__ float f_sqrt(float x) { float r; asm("sqrt.approx.f32 %0, %1;" : "=f"(r) : "f"(x)); return r; }
__device__ __forceinline__ float f_ex2(float x)  { float r; asm("ex2.approx.f32 %0, %1;"  : "=f"(r) : "f"(x)); return r; }

// ---- packed f32x2 (Blackwell, family-portable PTX) ----
__device__ __forceinline__ uint64_t pk2(float lo, float hi) {
    uint64_t r; asm("mov.b64 %0, {%1, %2};" : "=l"(r) : "f"(lo), "f"(hi)); return r;
}
__device__ __forceinline__ void upk2(float& lo, float& hi, uint64_t v) {
    asm("mov.b64 {%0, %1}, %2;" : "=f"(lo), "=f"(hi) : "l"(v));
}
__device__ __forceinline__ uint64_t fma2(uint64_t a, uint64_t b, uint64_t c) {
    uint64_t d; asm("fma.rn.f32x2 %0, %1, %2, %3;" : "=l"(d) : "l"(a), "l"(b), "l"(c)); return d;
}
__device__ __forceinline__ uint64_t mul2(uint64_t a, uint64_t b) {
    uint64_t d; asm("mul.rn.f32x2 %0, %1, %2;" : "=l"(d) : "l"(a), "l"(b)); return d;
}
__device__ __forceinline__ uint64_t add2(uint64_t a, uint64_t b) {
    uint64_t d; asm("add.rn.f32x2 %0, %1, %2;" : "=l"(d) : "l"(a), "l"(b)); return d;
}

__device__ __forceinline__ void cp_async16(uint32_t dst, const void* src) {
    asm volatile("cp.async.ca.shared.global [%0], [%1], 16;" :: "r"(dst), "l"(src));
}
__device__ __forceinline__ void cp_commit()   { asm volatile("cp.async.commit_group;"); }
__device__ __forceinline__ void cp_wait_all() { asm volatile("cp.async.wait_group 0;"); }
__device__ __forceinline__ void bar_group(int g) {
    asm volatile("bar.sync %0, %1;" :: "r"(g + 1), "r"(128) : "memory");
}

__device__ __forceinline__ void ldsm_x4(uint32_t& r0, uint32_t& r1, uint32_t& r2, uint32_t& r3, uint32_t addr) {
    asm volatile("ldmatrix.sync.aligned.m8n8.x4.shared.b16 {%0,%1,%2,%3}, [%4];"
                 : "=r"(r0), "=r"(r1), "=r"(r2), "=r"(r3) : "r"(addr));
}
__device__ __forceinline__ void mma16816(float* c, const uint32_t* a, const uint32_t* b) {
    asm volatile("mma.sync.aligned.m16n8k16.row.col.f32.bf16.bf16.f32 "
                 "{%0,%1,%2,%3}, {%4,%5,%6,%7}, {%8,%9}, {%0,%1,%2,%3};"
                 : "+f"(c[0]), "+f"(c[1]), "+f"(c[2]), "+f"(c[3])
                 : "r"(a[0]), "r"(a[1]), "r"(a[2]), "r"(a[3]), "r"(b[0]), "r"(b[1]));
}

// ---- prep: grid-stride unroll-4, single wave, MLP 8 ----
__global__ void prep_kernel(const float* __restrict__ z1, const float* __restrict__ z2) {
    const int tid0 = blockIdx.x * 256 + threadIdx.x;
    const int stride = PREP_BLOCKS * 256;
    #pragma unroll
    for (int u = 0; u < 4; ++u) {
        int idx = tid0 + u * stride;
        if (idx < TOTF) {
            int i = idx / D1;
            int k = idx - i * D1;
            float v1 = z1[idx], v2 = z2[idx];
            if (k == 0) { g_a0[i] = v1; g_b0[i] = v2; }
            else {
                g_A[(size_t)i * KDIM + k - 1] = __float2bfloat16(v1);
                g_B[(size_t)i * KDIM + k - 1] = __float2bfloat16(-v2);
            }
        }
    }
    if (tid0 < BATCH) { g_rowsum[tid0] = 0.f; g_colsum[tid0] = 0.f; }
    if (tid0 == 0) { g_loss = 0.f; g_ticket = 0u; }
}

// ---- persistent two-group fused HMMA GEMM + packed-f32x2 epilogue + diag capture ----
__global__ __launch_bounds__(256, 2) void hyper_gemm_kernel(int ncta) {
    extern __shared__ __align__(16) char sm[];
    const uint32_t sbase = smem_u32(sm);
    const int tid  = threadIdx.x;
    const int g    = tid >> 7;          // group 0/1
    const int gtid = tid & 127;
    const int wg   = gtid >> 5;         // warp in group 0..3
    const int lane = tid & 31;

    const int start = (int)(((long long)blockIdx.x * NTILE) / ncta);
    const int end   = (int)(((long long)(blockIdx.x + 1) * NTILE) / ncta);

    const int mw = wg * 32;
    const int lane8 = lane & 7, lm = lane >> 3;
    const int l4 = lane >> 2, l2 = lane & 3;

    const uint32_t aOff = (uint32_t)(mw + ((lm & 1) << 3) + lane8) * LDT_B + (uint32_t)((lm >> 1) << 4);
    const uint32_t bOff = (uint32_t)(((lm >> 1) << 3) + lane8) * LDT_B + (uint32_t)((lm & 1) << 4);

    const uint64_t R0p = pk2(RC0, RC0), R1p = pk2(RC1, RC1), R2p = pk2(RC2, RC2);

    int pos = start;
    while (pos < end) {
        const int tr = pos >> 7;
        const int r0 = tr * TM;
        const int row_end = min(end, (tr + 1) << 7);

        __syncthreads();                              // both groups done with previous row's A

        // load A strip (all 256 threads) + a0 vector
        #pragma unroll
        for (int it = 0; it < 8; ++it) {
            int idx = tid + it * 256;
            int row = idx >> 4, ch = idx & 15;
            cp_async16(sbase + SM_A + (uint32_t)row * LDT_B + (uint32_t)ch * 16u,
                       g_A + (size_t)(r0 + row) * KDIM + ch * 8);
        }
        if (tid < 32) cp_async16(sbase + SM_A0F + (uint32_t)tid * 16u, g_a0 + r0 + tid * 4);

        // first own tile of this row chunk (parity keyed to start+g)
        const int first = pos + (((start + g) ^ pos) & 1);
        const int n_own = (first < row_end) ? ((row_end - first + 1) >> 1) : 0;

        if (n_own > 0) {
            const int c0 = (first & 127) * TN;
            const uint32_t bb = sbase + SM_B + (uint32_t)(g * 2) * B_BUF;
            #pragma unroll
            for (int it = 0; it < 8; ++it) {
                int idx = gtid + it * 128;
                int row = idx >> 4, ch = idx & 15;
                cp_async16(bb + (uint32_t)row * LDT_B + (uint32_t)ch * 16u,
                           g_B + (size_t)(c0 + row) * KDIM + ch * 8);
            }
            if (gtid < 16)
                cp_async16(sbase + SM_B0F + (uint32_t)(g * 2) * 256u + (uint32_t)gtid * 16u,
                           g_b0 + c0 + gtid * 4);
        }
        cp_commit();
        cp_wait_all();
        __syncthreads();

        // rowsum partials held across the whole row chunk
        uint64_t rs2[4];
        #pragma unroll
        for (int q = 0; q < 4; ++q) rs2[q] = 0ull;

        int cur = 0;
        for (int i = 0; i < n_own; ++i) {
            const int t = first + 2 * i;
            const int c0 = (t & 127) * TN;
            const bool more = (i + 1 < n_own);

            if (more) {                               // prefetch next own tile under this compute
                const int nc0 = ((t + 2) & 127) * TN;
                const uint32_t bb = sbase + SM_B + (uint32_t)(g * 2 + (cur ^ 1)) * B_BUF;
                #pragma unroll
                for (int it = 0; it < 8; ++it) {
                    int idx = gtid + it * 128;
                    int row = idx >> 4, ch = idx & 15;
                    cp_async16(bb + (uint32_t)row * LDT_B + (uint32_t)ch * 16u,
                               g_B + (size_t)(nc0 + row) * KDIM + ch * 8);
                }
                if (gtid < 16)
                    cp_async16(sbase + SM_B0F + (uint32_t)(g * 2 + (cur ^ 1)) * 256u + (uint32_t)gtid * 16u,
                               g_b0 + nc0 + gtid * 4);
                cp_commit();
            }

            // ---- MMA ----
            float acc[2][8][4];
            #pragma unroll
            for (int mi = 0; mi < 2; ++mi)
                #pragma unroll
                for (int ni = 0; ni < 8; ++ni)
                    #pragma unroll
                    for (int q = 0; q < 4; ++q) acc[mi][ni][q] = -1.0f;   // fold the "-1"

            const uint32_t aBase = sbase + SM_A + aOff;
            const uint32_t bBase = sbase + SM_B + (uint32_t)(g * 2 + cur) * B_BUF + bOff;
            #pragma unroll
            for (int ks = 0; ks < 8; ++ks) {
                uint32_t a[2][4], b[8][2];
                ldsm_x4(a[0][0], a[0][1], a[0][2], a[0][3], aBase + ks * 32u);
                ldsm_x4(a[1][0], a[1][1], a[1][2], a[1][3], aBase + ks * 32u + 16u * LDT_B);
                #pragma unroll
                for (int p = 0; p < 4; ++p)
                    ldsm_x4(b[2 * p][0], b[2 * p][1], b[2 * p + 1][0], b[2 * p + 1][1],
                            bBase + ks * 32u + (uint32_t)p * 16u * LDT_B);
                #pragma unroll
                for (int mi = 0; mi < 2; ++mi)
                    #pragma unroll
                    for (int ni = 0; ni < 8; ++ni)
                        mma16816(acc[mi][ni], a[mi], b[ni]);
            }

            // ---- packed epilogue + diag capture ----
            const float* sa0 = (const float*)(sm + SM_A0F);
            const float* sb0 = (const float*)(sm + SM_B0F + (g * 2 + cur) * 256);
            const bool dtile = (r0 < c0 + TN) && (c0 < r0 + TM);   // tile straddles diagonal

            uint64_t csum2[8];
            #pragma unroll
            for (int q = 0; q < 8; ++q) csum2[q] = 0ull;

            #pragma unroll
            for (int mi = 0; mi < 2; ++mi) {
                const float a0A = sa0[mw + mi * 16 + l4];
                const float a0B = sa0[mw + mi * 16 + l4 + 8];
                const uint64_t aA2 = pk2(a0A, a0A);
                const uint64_t aB2 = pk2(a0B, a0B);
                #pragma unroll
                for (int ni = 0; ni < 8; ++ni) {
                    const int colL = ni * 8 + 2 * l2;
                    const uint64_t b2 = pk2(sb0[colL], sb0[colL + 1]);
                    #pragma unroll
                    for (int p = 0; p < 2; ++p) {      // p=0: rows A (q0,q1); p=1: rows B (q2,q3)
                        const uint64_t acc2 = pk2(acc[mi][ni][2 * p], acc[mi][ni][2 * p + 1]);
                        const uint64_t x2 = fma2(p ? aB2 : aA2, b2, acc2);   // {t-1} pair
                        float x0, x1; upk2(x0, x1, x2);
                        if (dtile) {                    // capture x_ii for the loss kernel
                            const int grow = r0 + mw + mi * 16 + l4 + (p ? 8 : 0);
                            const int gcol = c0 + colL;
                            if (grow == gcol)     g_diag[grow] = x0;
                            if (grow == gcol + 1) g_diag[grow] = x1;
                        }
                        const float w0 = f_sqrt(x0), w1 = f_sqrt(x1);
                        const uint64_t Rx2 = fma2(x2, fma2(x2, R2p, R1p), R0p);
                        const uint64_t m2 = mul2(pk2(w0, w1), Rx2);
                        float m0, m1; upk2(m0, m1, m2);
                        const float e0 = fminf(f_ex2(m0), E_CLAMP);   // x<0 -> NaN -> clamp
                        const float e1 = fminf(f_ex2(m1), E_CLAMP);
                        const uint64_t e2 = pk2(e0, e1);
                        rs2[mi * 2 + p] = add2(rs2[mi * 2 + p], e2);
                        csum2[ni] = add2(csum2[ni], e2);
                    }
                }
            }

            #pragma unroll
            for (int ni = 0; ni < 8; ++ni) {
                float lo, hi; upk2(lo, hi, csum2[ni]);
                #pragma unroll
                for (int h = 0; h < 2; ++h) {
                    float v = h ? hi : lo;
                    v += __shfl_xor_sync(0xffffffffu, v, 4);
                    v += __shfl_xor_sync(0xffffffffu, v, 8);
                    v += __shfl_xor_sync(0xffffffffu, v, 16);
                    if (l4 == 0)
                        atomicAdd(&g_colsum[c0 + ni * 8 + 2 * l2 + h], v);
                }
            }

            if (more) { cp_wait_all(); bar_group(g); }    // next buffer ready; group done with cur
            cur ^= 1;
        }

        // rowsum commit: once per chunk
        #pragma unroll
        for (int q = 0; q < 4; ++q) {
            float lo, hi; upk2(lo, hi, rs2[q]);
            float v = lo + hi;
            v += __shfl_xor_sync(0xffffffffu, v, 1);
            v += __shfl_xor_sync(0xffffffffu, v, 2);
            if (l2 == 0)
                atomicAdd(&g_rowsum[r0 + mw + (q >> 1) * 16 + (q & 1) * 8 + l4], v);
        }

        pos = row_end;
    }
}

// ---- loss: diag (from GEMM) + log-sums + ticket-gated finalize ----
__global__ void loss_kernel(float* __restrict__ out) {
    __shared__ float red[256];
    const int i = blockIdx.x * 256 + threadIdx.x;

    float t = fmaxf(1.0f + g_diag[i], TC_F);
    float s_ii = -acoshf(t) * (1.0f / 0.07f);

    float part = 0.5f * (logf(g_rowsum[i]) + logf(g_colsum[i])) - s_ii;
    red[threadIdx.x] = part;
    __syncthreads();
    for (int s = 128; s > 0; s >>= 1) {
        if (threadIdx.x < s) red[threadIdx.x] += red[threadIdx.x + s];
        __syncthreads();
    }
    if (threadIdx.x == 0) {
        atomicAdd(&g_loss, red[0]);
        __threadfence();
        unsigned tk = atomicAdd(&g_ticket, 1u);
        if (tk == gridDim.x - 1) {
            float total = atomicAdd(&g_loss, 0.0f);
            out[0] = total * (1.0f / (float)BATCH);
        }
    }
}

extern "C" void kernel_launch(void* const* d_in, const int* in_sizes, int n_in,
                              void* d_out, int out_size) {
    const float* z1 = (const float*)d_in[0];
    const float* z2 = (const float*)d_in[1];
    float* out = (float*)d_out;

    static int ncta = 0;
    if (ncta == 0) {
        int sms = 0;
        if (cudaDeviceGetAttribute(&sms, cudaDevAttrMultiProcessorCount, 0) != cudaSuccess || sms <= 0)
            sms = 148;
        ncta = 2 * sms;
        if (ncta > NTILE) ncta = NTILE;
        cudaFuncSetAttribute(hyper_gemm_kernel, cudaFuncAttributeMaxDynamicSharedMemorySize, SMEM_BYTES);
    }

    prep_kernel<<<PREP_BLOCKS, 256>>>(z1, z2);
    hyper_gemm_kernel<<<ncta, 256, SMEM_BYTES>>>(ncta);
    loss_kernel<<<BATCH / 256, 256>>>(out);
}